// round 3
// baseline (speedup 1.0000x reference)
#include <cuda_runtime.h>
#include <cstdint>

#define BB 64      // batch
#define TT 1024    // time steps
#define EE 512     // embedding
#define VV 256     // vocab

// ---------------- device scratch (static allocation, allowed) ----------------
__device__ float g_xwv[VV * EE];                 // XWV[v][o] = emb[v]·w_x[o] + b_cell[o]
__device__ float g_hs[(size_t)BB * TT * EE];     // h_t, layout [b][t][e]  (128 MB)
__device__ unsigned int g_bar[4 * 32];           // per-group counter, 128B apart

// =====================================================================
// Generic tiled GEMM:  C[M][N] = A[M][K] @ B[N][K]^T + bias[N]
// grid = (M/64, N/64), block = 256, BM=BN=64, BK=16, 4x4 microtile
// =====================================================================
__global__ void gemm_atb(const float* __restrict__ A, int lda,
                         const float* __restrict__ Bm, int ldb,
                         const float* __restrict__ bias,
                         float* __restrict__ C, int N, int K)
{
    __shared__ float As[16][64];
    __shared__ float Bs[16][64];

    const int tid  = threadIdx.x;
    const int m0   = blockIdx.x * 64;
    const int n0   = blockIdx.y * 64;
    const int tx   = tid & 15;
    const int ty   = tid >> 4;
    const int lrow = tid >> 2;         // 0..63
    const int lcol = (tid & 3) * 4;    // 0,4,8,12

    float acc[4][4];
#pragma unroll
    for (int i = 0; i < 4; ++i)
#pragma unroll
        for (int j = 0; j < 4; ++j) acc[i][j] = 0.0f;

    for (int k0 = 0; k0 < K; k0 += 16) {
        float4 av = *reinterpret_cast<const float4*>(A  + (size_t)(m0 + lrow) * lda + k0 + lcol);
        float4 bv = *reinterpret_cast<const float4*>(Bm + (size_t)(n0 + lrow) * ldb + k0 + lcol);
        As[lcol + 0][lrow] = av.x;
        As[lcol + 1][lrow] = av.y;
        As[lcol + 2][lrow] = av.z;
        As[lcol + 3][lrow] = av.w;
        Bs[lcol + 0][lrow] = bv.x;
        Bs[lcol + 1][lrow] = bv.y;
        Bs[lcol + 2][lrow] = bv.z;
        Bs[lcol + 3][lrow] = bv.w;
        __syncthreads();
#pragma unroll
        for (int kk = 0; kk < 16; ++kk) {
            float4 a = *reinterpret_cast<const float4*>(&As[kk][ty * 4]);
            float4 b = *reinterpret_cast<const float4*>(&Bs[kk][tx * 4]);
            acc[0][0] = fmaf(a.x, b.x, acc[0][0]);
            acc[0][1] = fmaf(a.x, b.y, acc[0][1]);
            acc[0][2] = fmaf(a.x, b.z, acc[0][2]);
            acc[0][3] = fmaf(a.x, b.w, acc[0][3]);
            acc[1][0] = fmaf(a.y, b.x, acc[1][0]);
            acc[1][1] = fmaf(a.y, b.y, acc[1][1]);
            acc[1][2] = fmaf(a.y, b.z, acc[1][2]);
            acc[1][3] = fmaf(a.y, b.w, acc[1][3]);
            acc[2][0] = fmaf(a.z, b.x, acc[2][0]);
            acc[2][1] = fmaf(a.z, b.y, acc[2][1]);
            acc[2][2] = fmaf(a.z, b.z, acc[2][2]);
            acc[2][3] = fmaf(a.z, b.w, acc[2][3]);
            acc[3][0] = fmaf(a.w, b.x, acc[3][0]);
            acc[3][1] = fmaf(a.w, b.y, acc[3][1]);
            acc[3][2] = fmaf(a.w, b.z, acc[3][2]);
            acc[3][3] = fmaf(a.w, b.w, acc[3][3]);
        }
        __syncthreads();
    }

#pragma unroll
    for (int i = 0; i < 4; ++i) {
        const size_t row = (size_t)(m0 + ty * 4 + i) * N + n0 + tx * 4;
#pragma unroll
        for (int j = 0; j < 4; ++j) {
            C[row + j] = acc[i][j] + __ldg(&bias[n0 + tx * 4 + j]);
        }
    }
}

// =====================================================================
// Barrier reset (runs before the recurrence each replay)
// =====================================================================
__global__ void reset_bar()
{
    if (threadIdx.x < 4) g_bar[threadIdx.x * 32] = 0u;
}

// =====================================================================
// Persistent recurrence kernel.
// grid = 128 CTAs = 4 batch-groups (16 batches) x 32 output-tiles (16 outs)
// block = 256 threads.
// Per step: h_prev (16x512) staged in smem, W_h slice (512x16) resident,
// 16 subtiles (4b x 4o) x 16 K-groups, smem k-reduction, tanh, STCG,
// per-group monotonic-counter barrier with release-atomics / acquire-spin.
// Dynamic smem: wsm 32KB + hsm 32KB + red 16KB = 80KB.
// =====================================================================
__global__ void rnn_scan(const int* __restrict__ x,
                         const float* __restrict__ h0,
                         const float* __restrict__ w_cell)
{
    extern __shared__ float sm[];
    float* wsm = sm;               // [e*16 + o_local]   e in [0,512)
    float* hsm = sm + 8192;        // [e*16 + b_local]
    float* red = sm + 16384;       // [(s*16+g)*16 + idx]

    const int tid = threadIdx.x;
    const int bt  = blockIdx.x >> 5;   // 0..3   batch group
    const int ot  = blockIdx.x & 31;   // 0..31  output tile
    const int b0  = bt * 16;
    const int o0  = ot * 16;

    // ---- load W_h slice once: w_h[o][e] = w_cell[o*1024 + 512 + e] ----
    for (int idx = tid; idx < 16 * 512; idx += 256) {
        const int o = idx >> 9;        // 0..15
        const int e = idx & 511;       // coalesced over e
        wsm[e * 16 + o] = w_cell[(size_t)(o0 + o) * 1024 + 512 + e];
    }

    // compute-phase mapping
    const int s  = tid & 15;           // subtile id
    const int g  = tid >> 4;           // k-group id (32 e each)
    const int bq = s >> 2;             // batch quad
    const int oq = s & 3;              // output quad

    // h-loader mapping
    const int lb = tid >> 4;           // 0..15 local batch row
    const int ec = (tid & 15) * 4;     // e chunk start

    // output mapping
    const int ob   = tid >> 4;         // local batch 0..15
    const int oo   = tid & 15;         // local out   0..15
    const int s2   = (ob >> 2) * 4 + (oo >> 2);
    const int idx2 = (ob & 3) * 4 + (oo & 3);

    const unsigned long long bar_ga =
        __cvta_generic_to_global((void*)&g_bar[bt * 32]);

    for (int t = 0; t < TT; ++t) {
        // ---- stage h_prev into hsm (transposed: [e][b]) ----
        if (t == 0) {
            for (int e = tid; e < EE; e += 256) {
                const float hv = __ldg(&h0[e]);
#pragma unroll
                for (int b = 0; b < 16; ++b) hsm[e * 16 + b] = hv;
            }
        } else {
            const float* src = g_hs + ((size_t)(b0 + lb) * TT + (t - 1)) * EE;
#pragma unroll
            for (int r = 0; r < 8; ++r) {
                const int e = ec + r * 64;
                const float4 v = __ldcg(reinterpret_cast<const float4*>(src + e));
                hsm[(e + 0) * 16 + lb] = v.x;
                hsm[(e + 1) * 16 + lb] = v.y;
                hsm[(e + 2) * 16 + lb] = v.z;
                hsm[(e + 3) * 16 + lb] = v.w;
            }
        }
        __syncthreads();

        // ---- partial GEMM: 4b x 4o x 32e per thread ----
        float acc[16];
#pragma unroll
        for (int i = 0; i < 16; ++i) acc[i] = 0.0f;
        const int eb = g * 32;
#pragma unroll 8
        for (int e = eb; e < eb + 32; ++e) {
            const float4 hv = *reinterpret_cast<const float4*>(hsm + e * 16 + bq * 4);
            const float4 wv = *reinterpret_cast<const float4*>(wsm + e * 16 + oq * 4);
            acc[0]  = fmaf(hv.x, wv.x, acc[0]);
            acc[1]  = fmaf(hv.x, wv.y, acc[1]);
            acc[2]  = fmaf(hv.x, wv.z, acc[2]);
            acc[3]  = fmaf(hv.x, wv.w, acc[3]);
            acc[4]  = fmaf(hv.y, wv.x, acc[4]);
            acc[5]  = fmaf(hv.y, wv.y, acc[5]);
            acc[6]  = fmaf(hv.y, wv.z, acc[6]);
            acc[7]  = fmaf(hv.y, wv.w, acc[7]);
            acc[8]  = fmaf(hv.z, wv.x, acc[8]);
            acc[9]  = fmaf(hv.z, wv.y, acc[9]);
            acc[10] = fmaf(hv.z, wv.z, acc[10]);
            acc[11] = fmaf(hv.z, wv.w, acc[11]);
            acc[12] = fmaf(hv.w, wv.x, acc[12]);
            acc[13] = fmaf(hv.w, wv.y, acc[13]);
            acc[14] = fmaf(hv.w, wv.z, acc[14]);
            acc[15] = fmaf(hv.w, wv.w, acc[15]);
        }
#pragma unroll
        for (int i = 0; i < 16; ++i) red[(s * 16 + g) * 16 + i] = acc[i];
        __syncthreads();

        // ---- k-reduction + xw gather + tanh + store h_t (through L2) ----
        {
            float sum = 0.0f;
#pragma unroll
            for (int gg = 0; gg < 16; ++gg) sum += red[(s2 * 16 + gg) * 16 + idx2];
            const int   v   = __ldg(x + (size_t)(b0 + ob) * TT + t);
            const float val = sum + __ldg(&g_xwv[(size_t)v * EE + o0 + oo]);
            __stcg(&g_hs[((size_t)(b0 + ob) * TT + t) * EE + o0 + oo], tanhf(val));
        }

        // ---- per-group barrier: release-add / acquire-spin (strong ops) ----
        if (t < TT - 1) {
            __threadfence();
            __syncthreads();
            if (tid == 0) {
                const unsigned int target = 32u * (unsigned int)(t + 1);
                unsigned int prev;
                asm volatile("atom.add.release.gpu.global.u32 %0, [%1], %2;"
                             : "=r"(prev) : "l"(bar_ga), "r"(1u) : "memory");
                if (prev + 1u < target) {
                    unsigned int cur;
                    do {
                        asm volatile("ld.acquire.gpu.global.u32 %0, [%1];"
                                     : "=r"(cur) : "l"(bar_ga) : "memory");
                    } while (cur < target);
                }
            }
            __syncthreads();
        }
    }
}

// =====================================================================
// host-side launch
// inputs: 0=x(int32 64x1024) 1=emb(256x512) 2=w_cell(512x1024)
//         3=b_cell(512) 4=w_head(256x512) 5=b_head(256) 6=h0(1x512)
// output: float32 (64,1024,256)
// =====================================================================
extern "C" void kernel_launch(void* const* d_in, const int* in_sizes, int n_in,
                              void* d_out, int out_size)
{
    const int*   x      = (const int*)  d_in[0];
    const float* emb    = (const float*)d_in[1];
    const float* w_cell = (const float*)d_in[2];
    const float* b_cell = (const float*)d_in[3];
    const float* w_head = (const float*)d_in[4];
    const float* b_head = (const float*)d_in[5];
    const float* h0     = (const float*)d_in[6];
    float*       out    = (float*)d_out;

    void* p_xwv = nullptr;
    void* p_hs  = nullptr;
    cudaGetSymbolAddress(&p_xwv, g_xwv);
    cudaGetSymbolAddress(&p_hs,  g_hs);

    // Phase 1: XWV[v][o] = emb @ w_x^T + b_cell   (256 x 512, K=512)
    {
        dim3 grid(VV / 64, EE / 64);
        gemm_atb<<<grid, 256>>>(emb, EE, w_cell, 2 * EE, b_cell,
                                (float*)p_xwv, EE, EE);
    }

    // Phase 2: recurrence
    reset_bar<<<1, 32>>>();
    cudaFuncSetAttribute(rnn_scan,
                         cudaFuncAttributeMaxDynamicSharedMemorySize, 82000);
    rnn_scan<<<128, 256, 81920>>>(x, h0, w_cell);

    // Phase 3: head GEMM  out = hs @ w_head^T + b_head  (65536 x 256, K=512)
    {
        dim3 grid((BB * TT) / 64, VV / 64);
        gemm_atb<<<grid, 256>>>((const float*)p_hs, EE, w_head, EE, b_head,
                                out, VV, EE);
    }
}